// round 4
// baseline (speedup 1.0000x reference)
#include <cuda_runtime.h>
#include <cuda_bf16.h>
#include <math.h>

// Shapes
#define BB 4
#define NN 16384
#define DD 64
#define HH 8
#define SPLITS 16
#define CT 128               // tokens per chunk/tile
#define L2_10K 0.4152410118609203f   // log2(10000)/32

typedef unsigned long long u64;

// ---- packed f32x2 helpers (sm_103a FFMA2 path) ----
__device__ __forceinline__ u64 pk2(float a, float b) {
    u64 r;
    asm("mov.b64 %0, {%1, %2};" : "=l"(r)
        : "r"(__float_as_uint(a)), "r"(__float_as_uint(b)));
    return r;
}
__device__ __forceinline__ void fma2(u64& d, u64 a, u64 b) {
    asm("fma.rn.f32x2 %0, %1, %2, %0;" : "+l"(d) : "l"(a), "l"(b));
}
__device__ __forceinline__ float2 up2(u64 a) {
    unsigned int lo, hi;
    asm("mov.b64 {%0, %1}, %2;" : "=r"(lo), "=r"(hi) : "l"(a));
    float2 r; r.x = __uint_as_float(lo); r.y = __uint_as_float(hi);
    return r;
}
__device__ __forceinline__ float wsum(float v) {
    #pragma unroll
    for (int o = 16; o > 0; o >>= 1) v += __shfl_xor_sync(0xffffffffu, v, o);
    return v;
}

// ---- scratch (no allocation allowed) ----
__device__ float g_kv_part[BB * HH * SPLITS * DD * DD];   // 8 MB
__device__ float g_M[BB * HH * DD * DD];                  // 512 KB

// =====================================================================
// Kernel A: per (b,h,split): k/v projection + LN + RoPE + kv = k^T v
// smem floats: xs 8448 | ks 8448 | vs 8448 | wk 4096 | wv 4096 | kva 4096
// =====================================================================
__global__ __launch_bounds__(256, 1)
void kv_kernel(const float* __restrict__ x, const float* __restrict__ pos,
               const float* __restrict__ Wk, const float* __restrict__ Wv)
{
    extern __shared__ float sm[];
    float* xs  = sm;            // [128][66]
    float* ks  = sm + 8448;     // [128][66]
    float* vs  = sm + 16896;    // [128][66]
    float* wk  = sm + 25344;    // [64][64]
    float* wv  = sm + 29440;    // [64][64]
    float* kva = sm + 33536;    // [64][64]

    const int tid = threadIdx.x;
    const int b = blockIdx.z, h = blockIdx.y, s = blockIdx.x;

    // Load per-head weight slices + zero kv accumulator
    #pragma unroll
    for (int r = 0; r < 16; r++) {
        int idx = tid + r * 256;
        int i = idx >> 6, o = idx & 63;
        wk[idx]  = Wk[i * 512 + h * 64 + o];
        wv[idx]  = Wv[i * 512 + h * 64 + o];
        kva[idx] = 0.f;
    }
    __syncthreads();

    const int lane = tid & 31, w = tid >> 5;
    const float inv_freq = exp2f(-(float)lane * L2_10K);

    const int og = tid & 7,  o0 = og * 8;
    const int tg = tid >> 3, t0 = tg * 4;
    const int d0 = (tid >> 3) * 2;      // kv-phase: 2 d rows
    const int e0 = (tid & 7) * 8;       // kv-phase: 8 e cols

    const int tok_per_blk = NN / SPLITS;            // 1024
    for (int c = 0; c < tok_per_blk / CT; c++) {    // 8 chunks
        const int tbase = s * tok_per_blk + c * CT;
        const float* xg = x + ((size_t)b * NN + tbase) * 64;

        // load x tile (coalesced), padded stride 66
        #pragma unroll
        for (int r = 0; r < 32; r++) {
            int idx = tid + r * 256;
            int t = idx >> 6, i = idx & 63;
            xs[t * 66 + i] = xg[idx];
        }
        __syncthreads();

        // ---- projection: k = xWk_h, v = xWv_h  (tile 4 tokens x 8 outs, f32x2) ----
        u64 ak[4][4], av[4][4];
        #pragma unroll
        for (int j = 0; j < 4; j++)
            #pragma unroll
            for (int p = 0; p < 4; p++) { ak[j][p] = 0ull; av[j][p] = 0ull; }

        #pragma unroll 8
        for (int i = 0; i < 64; i++) {
            u64 x2[4];
            #pragma unroll
            for (int j = 0; j < 4; j++) {
                float xv = xs[(t0 + j) * 66 + i];
                x2[j] = pk2(xv, xv);
            }
            ulonglong2 wk0 = *(const ulonglong2*)&wk[i * 64 + o0];
            ulonglong2 wk1 = *(const ulonglong2*)&wk[i * 64 + o0 + 4];
            ulonglong2 wv0 = *(const ulonglong2*)&wv[i * 64 + o0];
            ulonglong2 wv1 = *(const ulonglong2*)&wv[i * 64 + o0 + 4];
            u64 wkp[4] = { wk0.x, wk0.y, wk1.x, wk1.y };
            u64 wvp[4] = { wv0.x, wv0.y, wv1.x, wv1.y };
            #pragma unroll
            for (int j = 0; j < 4; j++)
                #pragma unroll
                for (int p = 0; p < 4; p++) {
                    fma2(ak[j][p], x2[j], wkp[p]);
                    fma2(av[j][p], x2[j], wvp[p]);
                }
        }
        #pragma unroll
        for (int j = 0; j < 4; j++)
            #pragma unroll
            for (int p = 0; p < 4; p++) {
                *(u64*)&ks[(t0 + j) * 66 + o0 + 2 * p] = ak[j][p];
                *(u64*)&vs[(t0 + j) * 66 + o0 + 2 * p] = av[j][p];
            }
        __syncthreads();

        // ---- LayerNorm(k), LayerNorm(v), RoPE(k): warp per token ----
        #pragma unroll 1
        for (int r = 0; r < 16; r++) {
            int t = w * 16 + r;
            float ka = ks[t * 66 + lane],      kb = ks[t * 66 + 32 + lane];
            float va = vs[t * 66 + lane],      vb = vs[t * 66 + 32 + lane];
            float ks1 = wsum(ka + kb);
            float ks2 = wsum(ka * ka + kb * kb);
            float vs1 = wsum(va + vb);
            float vs2 = wsum(va * va + vb * vb);
            float km = ks1 * (1.f / 64.f);
            float kr = rsqrtf(fmaxf(ks2 * (1.f / 64.f) - km * km, 0.f) + 1e-5f);
            float vm = vs1 * (1.f / 64.f);
            float vr = rsqrtf(fmaxf(vs2 * (1.f / 64.f) - vm * vm, 0.f) + 1e-5f);
            float kna = (ka - km) * kr, knb = (kb - km) * kr;
            float vna = (va - vm) * vr, vnb = (vb - vm) * vr;
            float pp = pos[(size_t)b * NN + tbase + t];
            float f = pp * 64.f * inv_freq;
            float sn_, cn_;
            sincosf(f, &sn_, &cn_);
            ks[t * 66 + lane]      = kna * cn_ - knb * sn_;
            ks[t * 66 + 32 + lane] = knb * cn_ + kna * sn_;
            vs[t * 66 + lane]      = vna;
            vs[t * 66 + 32 + lane] = vnb;
        }
        __syncthreads();

        // ---- kv[d][e] += sum_t k[t][d] * v[t][e]  (tile 2d x 8e, f32x2) ----
        u64 a[2][4];
        #pragma unroll
        for (int dj = 0; dj < 2; dj++)
            #pragma unroll
            for (int p = 0; p < 4; p++)
                a[dj][p] = *(u64*)&kva[(d0 + dj) * 64 + e0 + 2 * p];

        #pragma unroll 8
        for (int t = 0; t < CT; t++) {
            float k0 = ks[t * 66 + d0], k1 = ks[t * 66 + d0 + 1];
            u64 kk0 = pk2(k0, k0), kk1 = pk2(k1, k1);
            u64 vp[4];
            #pragma unroll
            for (int p = 0; p < 4; p++)
                vp[p] = *(const u64*)&vs[t * 66 + e0 + 2 * p];
            #pragma unroll
            for (int p = 0; p < 4; p++) {
                fma2(a[0][p], kk0, vp[p]);
                fma2(a[1][p], kk1, vp[p]);
            }
        }
        #pragma unroll
        for (int dj = 0; dj < 2; dj++)
            #pragma unroll
            for (int p = 0; p < 4; p++)
                *(u64*)&kva[(d0 + dj) * 64 + e0 + 2 * p] = a[dj][p];
        __syncthreads();
    }

    // write this split's partial kv
    float* dst = g_kv_part + ((size_t)(b * HH + h) * SPLITS + s) * 4096;
    #pragma unroll
    for (int r = 0; r < 16; r++) {
        int idx = tid + r * 256;
        dst[idx] = kva[idx];
    }
}

// =====================================================================
// Kernel B: reduce kv splits, M_h = (kv_h @ Wo_h) / N
// =====================================================================
__global__ __launch_bounds__(256, 1)
void m_kernel(const float* __restrict__ Wo)
{
    __shared__ float kvs[64 * 66];
    __shared__ float wo[64 * 64];
    const int tid = threadIdx.x;
    const int h = blockIdx.x, b = blockIdx.y;
    const float* src = g_kv_part + (size_t)(b * HH + h) * SPLITS * 4096;

    #pragma unroll
    for (int r = 0; r < 16; r++) {
        int idx = tid + r * 256;
        float acc = 0.f;
        #pragma unroll
        for (int s = 0; s < SPLITS; s++) acc += src[s * 4096 + idx];
        int i = idx >> 6, j = idx & 63;
        kvs[i * 66 + j] = acc;
        wo[idx] = Wo[(h * 64 + i) * 64 + j];
    }
    __syncthreads();

    const int i0 = (tid >> 3) * 2;
    const int d0 = (tid & 7) * 8;
    u64 a[2][4];
    #pragma unroll
    for (int ij = 0; ij < 2; ij++)
        #pragma unroll
        for (int p = 0; p < 4; p++) a[ij][p] = 0ull;

    #pragma unroll 8
    for (int j = 0; j < 64; j++) {
        float k0 = kvs[i0 * 66 + j], k1 = kvs[(i0 + 1) * 66 + j];
        u64 p0 = pk2(k0, k0), p1 = pk2(k1, k1);
        u64 wp[4];
        #pragma unroll
        for (int p = 0; p < 4; p++)
            wp[p] = *(const u64*)&wo[j * 64 + d0 + 2 * p];
        #pragma unroll
        for (int p = 0; p < 4; p++) {
            fma2(a[0][p], p0, wp[p]);
            fma2(a[1][p], p1, wp[p]);
        }
    }
    const float sc = 1.f / (float)NN;
    float* dst = g_M + ((size_t)b * 512 + h * 64) * 64;
    #pragma unroll
    for (int ij = 0; ij < 2; ij++)
        #pragma unroll
        for (int p = 0; p < 4; p++) {
            float2 v = up2(a[ij][p]);
            dst[(i0 + ij) * 64 + d0 + 2 * p]     = v.x * sc;
            dst[(i0 + ij) * 64 + d0 + 2 * p + 1] = v.y * sc;
        }
}

// =====================================================================
// Kernel C: out = sum_h RoPE(x @ Wq_h) @ M_h
// smem floats: xs 8448 | qs 8448 | wq 4096 | m 4096 | cs 4096 | sn 4096
// =====================================================================
__global__ __launch_bounds__(256, 1)
void out_kernel(const float* __restrict__ x, const float* __restrict__ pos,
                const float* __restrict__ Wq, float* __restrict__ out)
{
    extern __shared__ float sm[];
    float* xs = sm;             // [128][66]
    float* qs = sm + 8448;      // [128][66]
    float* wq = sm + 16896;     // [64][64]
    float* mm = sm + 20992;     // [64][64]
    float* cs = sm + 25088;     // [128][32]
    float* sn = sm + 29184;     // [128][32]

    const int tid = threadIdx.x;
    const int b = blockIdx.y;
    const int tbase = blockIdx.x * CT;
    const float* xg = x + ((size_t)b * NN + tbase) * 64;

    #pragma unroll
    for (int r = 0; r < 32; r++) {
        int idx = tid + r * 256;
        int t = idx >> 6, i = idx & 63;
        xs[t * 66 + i] = xg[idx];
    }
    // sincos table for this tile (shared across heads)
    #pragma unroll 1
    for (int r = 0; r < 16; r++) {
        int idx = tid + r * 256;
        int t = idx >> 5, l = idx & 31;
        float pp = pos[(size_t)b * NN + tbase + t];
        float f = pp * 64.f * exp2f(-(float)l * L2_10K);
        float s_, c_;
        sincosf(f, &s_, &c_);
        cs[idx] = c_;
        sn[idx] = s_;
    }
    __syncthreads();

    const int og = tid & 7,  o0 = og * 8;
    const int tg = tid >> 3, t0 = tg * 4;
    const int lane = tid & 31, w = tid >> 5;

    u64 oa[4][4];
    #pragma unroll
    for (int j = 0; j < 4; j++)
        #pragma unroll
        for (int p = 0; p < 4; p++) oa[j][p] = 0ull;

    for (int h = 0; h < HH; h++) {
        #pragma unroll
        for (int r = 0; r < 16; r++) {
            int idx = tid + r * 256;
            int i = idx >> 6, o = idx & 63;
            wq[idx] = Wq[i * 512 + h * 64 + o];
            mm[idx] = g_M[((size_t)b * 512 + h * 64 + i) * 64 + o];
        }
        __syncthreads();

        // q = x @ Wq_h
        u64 aq[4][4];
        #pragma unroll
        for (int j = 0; j < 4; j++)
            #pragma unroll
            for (int p = 0; p < 4; p++) aq[j][p] = 0ull;

        #pragma unroll 8
        for (int i = 0; i < 64; i++) {
            u64 x2[4];
            #pragma unroll
            for (int j = 0; j < 4; j++) {
                float xv = xs[(t0 + j) * 66 + i];
                x2[j] = pk2(xv, xv);
            }
            ulonglong2 w0 = *(const ulonglong2*)&wq[i * 64 + o0];
            ulonglong2 w1 = *(const ulonglong2*)&wq[i * 64 + o0 + 4];
            u64 wp[4] = { w0.x, w0.y, w1.x, w1.y };
            #pragma unroll
            for (int j = 0; j < 4; j++)
                #pragma unroll
                for (int p = 0; p < 4; p++)
                    fma2(aq[j][p], x2[j], wp[p]);
        }
        #pragma unroll
        for (int j = 0; j < 4; j++)
            #pragma unroll
            for (int p = 0; p < 4; p++)
                *(u64*)&qs[(t0 + j) * 66 + o0 + 2 * p] = aq[j][p];
        __syncthreads();

        // RoPE(q): warp per token
        #pragma unroll 1
        for (int r = 0; r < 16; r++) {
            int t = w * 16 + r;
            float qa = qs[t * 66 + lane], qb = qs[t * 66 + 32 + lane];
            float cc = cs[t * 32 + lane], ss = sn[t * 32 + lane];
            qs[t * 66 + lane]      = qa * cc - qb * ss;
            qs[t * 66 + 32 + lane] = qb * cc + qa * ss;
        }
        __syncthreads();

        // out += q_rope @ M_h
        #pragma unroll 8
        for (int i = 0; i < 64; i++) {
            u64 q2[4];
            #pragma unroll
            for (int j = 0; j < 4; j++) {
                float qv = qs[(t0 + j) * 66 + i];
                q2[j] = pk2(qv, qv);
            }
            ulonglong2 m0 = *(const ulonglong2*)&mm[i * 64 + o0];
            ulonglong2 m1 = *(const ulonglong2*)&mm[i * 64 + o0 + 4];
            u64 mp[4] = { m0.x, m0.y, m1.x, m1.y };
            #pragma unroll
            for (int j = 0; j < 4; j++)
                #pragma unroll
                for (int p = 0; p < 4; p++)
                    fma2(oa[j][p], q2[j], mp[p]);
        }
        __syncthreads();   // protect wq/mm/qs before next head
    }

    float* outg = out + ((size_t)b * NN + tbase) * 64;
    #pragma unroll
    for (int j = 0; j < 4; j++)
        #pragma unroll
        for (int p = 0; p < 4; p++) {
            float2 v = up2(oa[j][p]);
            *(float2*)&outg[(t0 + j) * 64 + o0 + 2 * p] = v;
        }
}

// =====================================================================
extern "C" void kernel_launch(void* const* d_in, const int* in_sizes, int n_in,
                              void* d_out, int out_size)
{
    const float* x   = (const float*)d_in[0];
    const float* pos = (const float*)d_in[1];
    const float* Wq  = (const float*)d_in[2];
    const float* Wk  = (const float*)d_in[3];
    const float* Wv  = (const float*)d_in[4];
    const float* Wo  = (const float*)d_in[5];
    float* out = (float*)d_out;

    const int SMEM_A = 37632 * 4;   // 150528 B
    const int SMEM_C = 33280 * 4;   // 133120 B
    cudaFuncSetAttribute(kv_kernel,  cudaFuncAttributeMaxDynamicSharedMemorySize, SMEM_A);
    cudaFuncSetAttribute(out_kernel, cudaFuncAttributeMaxDynamicSharedMemorySize, SMEM_C);

    kv_kernel<<<dim3(SPLITS, HH, BB), 256, SMEM_A>>>(x, pos, Wk, Wv);
    m_kernel<<<dim3(HH, BB), 256>>>(Wo);
    out_kernel<<<dim3(NN / CT, BB), 256, SMEM_C>>>(x, pos, Wq, out);
}

// round 5
// speedup vs baseline: 1.0244x; 1.0244x over previous
#include <cuda_runtime.h>
#include <math.h>

#define BB 4
#define NN 16384
#define DD 64
#define HH 8
#define SPLITS 64
#define CT 128
#define XSS 68
#define L2_10K 0.4152410118609203f   // log2(10000)/32

typedef unsigned long long u64;

__device__ __forceinline__ u64 pk2(float a, float b) {
    u64 r;
    asm("mov.b64 %0, {%1, %2};" : "=l"(r)
        : "r"(__float_as_uint(a)), "r"(__float_as_uint(b)));
    return r;
}
__device__ __forceinline__ float2 up2(u64 a) {
    unsigned int lo, hi;
    asm("mov.b64 {%0, %1}, %2;" : "=r"(lo), "=r"(hi) : "l"(a));
    float2 r; r.x = __uint_as_float(lo); r.y = __uint_as_float(hi);
    return r;
}
__device__ __forceinline__ void fma2(u64& d, u64 a, u64 b) {
    asm("fma.rn.f32x2 %0, %1, %2, %0;" : "+l"(d) : "l"(a), "l"(b));
}
__device__ __forceinline__ u64 add2(u64 a, u64 b) {
    u64 r; asm("add.rn.f32x2 %0, %1, %2;" : "=l"(r) : "l"(a), "l"(b)); return r;
}
__device__ __forceinline__ u64 mul2(u64 a, u64 b) {
    u64 r; asm("mul.rn.f32x2 %0, %1, %2;" : "=l"(r) : "l"(a), "l"(b)); return r;
}

// scratch (static, no allocation)
__device__ float g_kv_part[BB * HH * SPLITS * DD * DD];   // 33.5 MB
__device__ float g_M[BB * HH * DD * DD];                  // 512 KB
__device__ float g_tabc[BB * NN * 32];                    // 8 MB
__device__ float g_tabs[BB * NN * 32];                    // 8 MB

// =====================================================================
// Kernel 0: RoPE cos/sin table
// =====================================================================
__global__ __launch_bounds__(256)
void tab_kernel(const float* __restrict__ pos)
{
    int idx = blockIdx.x * 256 + threadIdx.x;
    int fi = idx & 31;
    int bt = idx >> 5;
    float f = pos[bt] * 64.f * exp2f(-(float)fi * L2_10K);
    float s_, c_;
    sincosf(f, &s_, &c_);
    g_tabc[idx] = c_;
    g_tabs[idx] = s_;
}

// =====================================================================
// Kernel A: per (b,h,split): k/v proj (warp-specialized) + reg LN/RoPE
//           + kv = k^T v (register accumulators)
// smem: xs(=vs)[128][68] + ks[128][68] + wk[64][64] + wv[64][64] = 100 KB
// =====================================================================
__global__ __launch_bounds__(256, 2)
void kv_kernel(const float* __restrict__ x,
               const float* __restrict__ Wk, const float* __restrict__ Wv)
{
    extern __shared__ float sm[];
    float* xs = sm;                     // [128][68], becomes vs
    float* ks = sm + CT * XSS;          // [128][68]
    float* wk = sm + 2 * CT * XSS;      // [64][64]
    float* wv = wk + 4096;              // [64][64]

    const int tid = threadIdx.x;
    const int b = blockIdx.z, h = blockIdx.y, s = blockIdx.x;

    #pragma unroll
    for (int r = 0; r < 16; r++) {
        int idx = tid + r * 256;
        int i = idx >> 6, o = idx & 63;
        wk[idx] = Wk[i * 512 + h * 64 + o];
        wv[idx] = Wv[i * 512 + h * 64 + o];
    }

    const bool kwarp = (tid < 128);
    const int local = tid & 127;
    const int og = local & 7, tg = local >> 3;   // 16 token-groups x 8 out-groups
    const int o0 = og * 8;
    const float* W = kwarp ? wk : wv;
    float* dstbuf = kwarp ? ks : xs;             // vs aliases xs
    const float sgn = (og < 4) ? -1.f : 1.f;
    const u64 sgn2 = pk2(sgn, sgn);
    const int fbase = o0 & 31;

    // kv accumulator tile: 2 d-rows x 8 e-cols per thread (all 256 threads)
    const int d0 = (tid >> 3) * 2;
    const int e0 = (tid & 7) * 8;
    u64 kva[2][4];
    #pragma unroll
    for (int dj = 0; dj < 2; dj++)
        #pragma unroll
        for (int p = 0; p < 4; p++) kva[dj][p] = 0ull;

    __syncthreads();

    const int tok_per_blk = NN / SPLITS;            // 256
    #pragma unroll 1
    for (int c = 0; c < tok_per_blk / CT; c++) {    // 2 chunks
        const int tbase = s * tok_per_blk + c * CT;
        const float* xg = x + ((size_t)b * NN + tbase) * 64;

        __syncthreads();    // previous chunk's vs readers done
        #pragma unroll
        for (int r = 0; r < 32; r++) {
            int idx = tid + r * 256;
            xs[(idx >> 6) * XSS + (idx & 63)] = xg[idx];
        }
        __syncthreads();

        // ---- projection: 8 interleaved tokens (t = tg+16j) x 8 outputs ----
        u64 acc[8][4];
        #pragma unroll
        for (int j = 0; j < 8; j++)
            #pragma unroll
            for (int p = 0; p < 4; p++) acc[j][p] = 0ull;

        #pragma unroll 4
        for (int i = 0; i < 64; i++) {
            u64 x2[8];
            #pragma unroll
            for (int j = 0; j < 8; j++) {
                float xv = xs[(tg + 16 * j) * XSS + i];
                x2[j] = pk2(xv, xv);
            }
            ulonglong2 w0 = *(const ulonglong2*)&W[i * 64 + o0];
            ulonglong2 w1 = *(const ulonglong2*)&W[i * 64 + o0 + 4];
            u64 wp[4] = { w0.x, w0.y, w1.x, w1.y };
            #pragma unroll
            for (int j = 0; j < 8; j++)
                #pragma unroll
                for (int p = 0; p < 4; p++)
                    fma2(acc[j][p], x2[j], wp[p]);
        }
        __syncthreads();    // xs reads done (v-warps will overwrite it)

        // ---- LN in registers (8-lane groups) + RoPE for k-warps ----
        #pragma unroll
        for (int j = 0; j < 8; j++) {
            const int t = tg + 16 * j;
            u64 t01 = add2(acc[j][0], acc[j][1]);
            u64 t23 = add2(acc[j][2], acc[j][3]);
            float2 sf = up2(add2(t01, t23));
            float s1 = sf.x + sf.y;
            u64 q01 = add2(mul2(acc[j][0], acc[j][0]), mul2(acc[j][1], acc[j][1]));
            u64 q23 = add2(mul2(acc[j][2], acc[j][2]), mul2(acc[j][3], acc[j][3]));
            float2 qf = up2(add2(q01, q23));
            float s2 = qf.x + qf.y;
            #pragma unroll
            for (int m = 1; m < 8; m <<= 1) {
                s1 += __shfl_xor_sync(0xffffffffu, s1, m);
                s2 += __shfl_xor_sync(0xffffffffu, s2, m);
            }
            float mean = s1 * (1.f / 64.f);
            float var  = fmaxf(s2 * (1.f / 64.f) - mean * mean, 0.f);
            float rs   = rsqrtf(var + 1e-5f);
            float mr   = -mean * rs;
            u64 rs2 = pk2(rs, rs), mr2 = pk2(mr, mr);
            u64 kn[4];
            #pragma unroll
            for (int p = 0; p < 4; p++) { kn[p] = mr2; fma2(kn[p], acc[j][p], rs2); }

            if (kwarp) {   // RoPE (warp-uniform branch)
                u64 pn[4];
                #pragma unroll
                for (int p = 0; p < 4; p++)
                    pn[p] = __shfl_xor_sync(0xffffffffu, kn[p], 4);
                const float* tc = &g_tabc[((size_t)(b * NN + tbase + t)) * 32 + fbase];
                const float* ts = &g_tabs[((size_t)(b * NN + tbase + t)) * 32 + fbase];
                float4 c0 = *(const float4*)tc;
                float4 c1 = *(const float4*)(tc + 4);
                float4 s0 = *(const float4*)ts;
                float4 s1v = *(const float4*)(ts + 4);
                u64 cc[4] = { pk2(c0.x, c0.y), pk2(c0.z, c0.w),
                              pk2(c1.x, c1.y), pk2(c1.z, c1.w) };
                u64 ss[4] = { pk2(s0.x, s0.y), pk2(s0.z, s0.w),
                              pk2(s1v.x, s1v.y), pk2(s1v.z, s1v.w) };
                #pragma unroll
                for (int p = 0; p < 4; p++) {
                    u64 r = mul2(kn[p], cc[p]);
                    fma2(r, pn[p], mul2(ss[p], sgn2));
                    kn[p] = r;
                }
            }
            #pragma unroll
            for (int sr = 0; sr < 4; sr++) {       // rotated store order
                int p = (sr + og) & 3;
                *(u64*)&dstbuf[t * XSS + o0 + 2 * p] = kn[p];
            }
        }
        __syncthreads();

        // ---- kv[d][e] += sum_t k[t][d]*v[t][e] ----
        #pragma unroll 8
        for (int t = 0; t < CT; t++) {
            float k0 = ks[t * XSS + d0], k1 = ks[t * XSS + d0 + 1];
            u64 kk0 = pk2(k0, k0), kk1 = pk2(k1, k1);
            ulonglong2 v0 = *(const ulonglong2*)&xs[t * XSS + e0];
            ulonglong2 v1 = *(const ulonglong2*)&xs[t * XSS + e0 + 4];
            u64 vp[4] = { v0.x, v0.y, v1.x, v1.y };
            #pragma unroll
            for (int p = 0; p < 4; p++) {
                fma2(kva[0][p], kk0, vp[p]);
                fma2(kva[1][p], kk1, vp[p]);
            }
        }
    }

    float* dst = g_kv_part + ((size_t)((b * HH + h) * SPLITS + s)) * 4096;
    #pragma unroll
    for (int dj = 0; dj < 2; dj++)
        #pragma unroll
        for (int p = 0; p < 4; p++)
            *(u64*)&dst[(d0 + dj) * 64 + e0 + 2 * p] = kva[dj][p];
}

// =====================================================================
// Kernel B: reduce splits, M_h = (kv_h @ Wo_h) / N
// =====================================================================
__global__ __launch_bounds__(256, 1)
void m_kernel(const float* __restrict__ Wo)
{
    __shared__ float kvs[64 * 66];
    __shared__ float wo[64 * 64];
    const int tid = threadIdx.x;
    const int h = blockIdx.x, b = blockIdx.y;
    const float* src = g_kv_part + (size_t)(b * HH + h) * SPLITS * 4096;

    #pragma unroll
    for (int r = 0; r < 16; r++) {
        int idx = tid + r * 256;
        float acc = 0.f;
        #pragma unroll 4
        for (int s = 0; s < SPLITS; s++) acc += src[s * 4096 + idx];
        int i = idx >> 6, j = idx & 63;
        kvs[i * 66 + j] = acc;
        wo[idx] = Wo[(h * 64 + i) * 64 + j];
    }
    __syncthreads();

    const int i0 = (tid >> 3) * 2;
    const int d0 = (tid & 7) * 8;
    u64 a[2][4];
    #pragma unroll
    for (int ij = 0; ij < 2; ij++)
        #pragma unroll
        for (int p = 0; p < 4; p++) a[ij][p] = 0ull;

    #pragma unroll 8
    for (int j = 0; j < 64; j++) {
        float k0 = kvs[i0 * 66 + j], k1 = kvs[(i0 + 1) * 66 + j];
        u64 p0 = pk2(k0, k0), p1 = pk2(k1, k1);
        ulonglong2 w0 = *(const ulonglong2*)&wo[j * 64 + d0];
        ulonglong2 w1 = *(const ulonglong2*)&wo[j * 64 + d0 + 4];
        u64 wp[4] = { w0.x, w0.y, w1.x, w1.y };
        #pragma unroll
        for (int p = 0; p < 4; p++) {
            fma2(a[0][p], p0, wp[p]);
            fma2(a[1][p], p1, wp[p]);
        }
    }
    const float sc = 1.f / (float)NN;
    const u64 sc2 = pk2(sc, sc);
    float* dst = g_M + ((size_t)(b * 512 + h * 64)) * 64;
    #pragma unroll
    for (int ij = 0; ij < 2; ij++)
        #pragma unroll
        for (int p = 0; p < 4; p++)
            *(u64*)&dst[(i0 + ij) * 64 + d0 + 2 * p] = mul2(a[ij][p], sc2);
}

// =====================================================================
// Kernel C: out = sum_h RoPE(x @ Wq_h) @ M_h
// smem: xs[128][68] + qs[128][68] + wq[64][64] + mm[64][64] = 100 KB
// =====================================================================
__global__ __launch_bounds__(256, 2)
void out_kernel(const float* __restrict__ x,
                const float* __restrict__ Wq, float* __restrict__ out)
{
    extern __shared__ float sm[];
    float* xs = sm;
    float* qs = sm + CT * XSS;
    float* wq = sm + 2 * CT * XSS;
    float* mm = wq + 4096;

    const int tid = threadIdx.x;
    const int b = blockIdx.y;
    const int tbase = blockIdx.x * CT;
    const float* xg = x + ((size_t)b * NN + tbase) * 64;

    #pragma unroll
    for (int r = 0; r < 32; r++) {
        int idx = tid + r * 256;
        xs[(idx >> 6) * XSS + (idx & 63)] = xg[idx];
    }

    const int og = tid & 7, tg = tid >> 3;    // 32 token-groups x 8 out-groups
    const int o0 = og * 8;
    const float sgn = (og < 4) ? -1.f : 1.f;
    const u64 sgn2 = pk2(sgn, sgn);
    const int fbase = o0 & 31;

    u64 oa[4][4];
    #pragma unroll
    for (int j = 0; j < 4; j++)
        #pragma unroll
        for (int p = 0; p < 4; p++) oa[j][p] = 0ull;

    __syncthreads();

    #pragma unroll 1
    for (int h = 0; h < HH; h++) {
        #pragma unroll
        for (int r = 0; r < 16; r++) {
            int idx = tid + r * 256;
            int i = idx >> 6, o = idx & 63;
            wq[idx] = Wq[i * 512 + h * 64 + o];
            mm[idx] = g_M[(size_t)(b * 512 + h * 64 + i) * 64 + o];
        }
        __syncthreads();

        // q = x @ Wq_h  : 4 tokens (t = tg+32j) x 8 outputs per thread
        u64 aq[4][4];
        #pragma unroll
        for (int j = 0; j < 4; j++)
            #pragma unroll
            for (int p = 0; p < 4; p++) aq[j][p] = 0ull;

        #pragma unroll 4
        for (int i = 0; i < 64; i++) {
            u64 x2[4];
            #pragma unroll
            for (int j = 0; j < 4; j++) {
                float xv = xs[(tg + 32 * j) * XSS + i];
                x2[j] = pk2(xv, xv);
            }
            ulonglong2 w0 = *(const ulonglong2*)&wq[i * 64 + o0];
            ulonglong2 w1 = *(const ulonglong2*)&wq[i * 64 + o0 + 4];
            u64 wp[4] = { w0.x, w0.y, w1.x, w1.y };
            #pragma unroll
            for (int j = 0; j < 4; j++)
                #pragma unroll
                for (int p = 0; p < 4; p++)
                    fma2(aq[j][p], x2[j], wp[p]);
        }

        // RoPE(q) in registers, single store to qs
        #pragma unroll
        for (int j = 0; j < 4; j++) {
            const int t = tg + 32 * j;
            u64 pn[4];
            #pragma unroll
            for (int p = 0; p < 4; p++)
                pn[p] = __shfl_xor_sync(0xffffffffu, aq[j][p], 4);
            const float* tc = &g_tabc[((size_t)(b * NN + tbase + t)) * 32 + fbase];
            const float* ts = &g_tabs[((size_t)(b * NN + tbase + t)) * 32 + fbase];
            float4 c0 = *(const float4*)tc;
            float4 c1 = *(const float4*)(tc + 4);
            float4 s0 = *(const float4*)ts;
            float4 s1v = *(const float4*)(ts + 4);
            u64 cc[4] = { pk2(c0.x, c0.y), pk2(c0.z, c0.w),
                          pk2(c1.x, c1.y), pk2(c1.z, c1.w) };
            u64 ss[4] = { pk2(s0.x, s0.y), pk2(s0.z, s0.w),
                          pk2(s1v.x, s1v.y), pk2(s1v.z, s1v.w) };
            #pragma unroll
            for (int sr = 0; sr < 4; sr++) {
                int p = (sr + og) & 3;
                u64 r = mul2(aq[j][p], cc[p]);
                fma2(r, pn[p], mul2(ss[p], sgn2));
                *(u64*)&qs[t * XSS + o0 + 2 * p] = r;
            }
        }
        __syncthreads();

        // out += q_rope @ M_h
        #pragma unroll 4
        for (int i = 0; i < 64; i++) {
            u64 q2[4];
            #pragma unroll
            for (int j = 0; j < 4; j++) {
                float qv = qs[(tg + 32 * j) * XSS + i];
                q2[j] = pk2(qv, qv);
            }
            ulonglong2 m0 = *(const ulonglong2*)&mm[i * 64 + o0];
            ulonglong2 m1 = *(const ulonglong2*)&mm[i * 64 + o0 + 4];
            u64 mp[4] = { m0.x, m0.y, m1.x, m1.y };
            #pragma unroll
            for (int j = 0; j < 4; j++)
                #pragma unroll
                for (int p = 0; p < 4; p++)
                    fma2(oa[j][p], q2[j], mp[p]);
        }
        __syncthreads();
    }

    float* outg = out + ((size_t)b * NN + tbase) * 64;
    #pragma unroll
    for (int j = 0; j < 4; j++)
        #pragma unroll
        for (int p = 0; p < 4; p++)
            *(u64*)&outg[(tg + 32 * j) * 64 + o0 + 2 * p] = oa[j][p];
}

// =====================================================================
extern "C" void kernel_launch(void* const* d_in, const int* in_sizes, int n_in,
                              void* d_out, int out_size)
{
    const float* x   = (const float*)d_in[0];
    const float* pos = (const float*)d_in[1];
    const float* Wq  = (const float*)d_in[2];
    const float* Wk  = (const float*)d_in[3];
    const float* Wv  = (const float*)d_in[4];
    const float* Wo  = (const float*)d_in[5];
    float* out = (float*)d_out;

    const int SMEM_KV  = (2 * CT * XSS + 2 * 4096) * 4;   // 102400 B
    const int SMEM_OUT = (2 * CT * XSS + 2 * 4096) * 4;   // 102400 B
    cudaFuncSetAttribute(kv_kernel,  cudaFuncAttributeMaxDynamicSharedMemorySize, SMEM_KV);
    cudaFuncSetAttribute(out_kernel, cudaFuncAttributeMaxDynamicSharedMemorySize, SMEM_OUT);

    tab_kernel<<<BB * NN * 32 / 256, 256>>>(pos);
    kv_kernel<<<dim3(SPLITS, HH, BB), 256, SMEM_KV>>>(x, Wk, Wv);
    m_kernel<<<dim3(HH, BB), 256>>>(Wo);
    out_kernel<<<dim3(NN / CT, BB), 256, SMEM_OUT>>>(x, Wq, out);
}

// round 6
// speedup vs baseline: 1.4074x; 1.3738x over previous
#include <cuda_runtime.h>
#include <math.h>

#define BB 4
#define NN 16384
#define DD 64
#define HH 8
#define SPLITS 64
#define CT 128
#define XSS 68
#define L2_10K 0.4152410118609203f   // log2(10000)/32

typedef unsigned long long u64;

__device__ __forceinline__ u64 pk2(float a, float b) {
    u64 r;
    asm("mov.b64 %0, {%1, %2};" : "=l"(r)
        : "r"(__float_as_uint(a)), "r"(__float_as_uint(b)));
    return r;
}
__device__ __forceinline__ float2 up2(u64 a) {
    unsigned int lo, hi;
    asm("mov.b64 {%0, %1}, %2;" : "=r"(lo), "=r"(hi) : "l"(a));
    float2 r; r.x = __uint_as_float(lo); r.y = __uint_as_float(hi);
    return r;
}
__device__ __forceinline__ void fma2(u64& d, u64 a, u64 b) {
    asm("fma.rn.f32x2 %0, %1, %2, %0;" : "+l"(d) : "l"(a), "l"(b));
}
__device__ __forceinline__ u64 add2(u64 a, u64 b) {
    u64 r; asm("add.rn.f32x2 %0, %1, %2;" : "=l"(r) : "l"(a), "l"(b)); return r;
}
__device__ __forceinline__ u64 mul2(u64 a, u64 b) {
    u64 r; asm("mul.rn.f32x2 %0, %1, %2;" : "=l"(r) : "l"(a), "l"(b)); return r;
}

// scratch (static, no allocation)
__device__ float g_kv_part[BB * HH * SPLITS * DD * DD];   // 33.5 MB
__device__ float g_M[BB * HH * DD * DD];                  // 512 KB
__device__ float g_tabc[BB * NN * 32];                    // 8 MB
__device__ float g_tabs[BB * NN * 32];                    // 8 MB

// =====================================================================
// Kernel 0: RoPE cos/sin table
// =====================================================================
__global__ __launch_bounds__(256)
void tab_kernel(const float* __restrict__ pos)
{
    int idx = blockIdx.x * 256 + threadIdx.x;
    int fi = idx & 31;
    int bt = idx >> 5;
    float f = pos[bt] * 64.f * exp2f(-(float)fi * L2_10K);
    float s_, c_;
    sincosf(f, &s_, &c_);
    g_tabc[idx] = c_;
    g_tabs[idx] = s_;
}

// =====================================================================
// Kernel A: per (b,h,split): k/v proj (warp-specialized) + reg LN/RoPE
//           + kv = k^T v (register accumulators)
// smem: xs(=vs)[128][68] + ks[128][68] + wk[64][64] + wv[64][64] = 100 KB
// =====================================================================
__global__ __launch_bounds__(256, 2)
void kv_kernel(const float* __restrict__ x,
               const float* __restrict__ Wk, const float* __restrict__ Wv)
{
    extern __shared__ float sm[];
    float* xs = sm;                     // [128][68], becomes vs
    float* ks = sm + CT * XSS;          // [128][68]
    float* wk = sm + 2 * CT * XSS;      // [64][64]
    float* wv = wk + 4096;              // [64][64]

    const int tid = threadIdx.x;
    const int b = blockIdx.z, h = blockIdx.y, s = blockIdx.x;

    #pragma unroll
    for (int r = 0; r < 16; r++) {
        int idx = tid + r * 256;
        int i = idx >> 6, o = idx & 63;
        wk[idx] = Wk[i * 512 + h * 64 + o];
        wv[idx] = Wv[i * 512 + h * 64 + o];
    }

    const bool kwarp = (tid < 128);
    const int local = tid & 127;
    const int lane  = local & 31;
    const int wl    = local >> 5;        // 0..3
    const int og    = lane >> 2;         // 0..7  (HIGH lane bits -> conflict-free LDS.128)
    const int tl    = lane & 3;
    const int tg    = wl * 4 + tl;       // 0..15 token group
    const int o0    = og * 8;
    const float* W  = kwarp ? wk : wv;
    float* dstbuf   = kwarp ? ks : xs;   // vs aliases xs
    const float sgn = (og < 4) ? -1.f : 1.f;
    const u64 sgn2  = pk2(sgn, sgn);
    const int fbase = o0 & 31;

    // kv accumulator tile: 2 d-rows x 8 e-cols per thread (all 256 threads)
    const int lane8 = tid & 31;
    const int eg = lane8 >> 2;                       // 0..7
    const int dg = (tid >> 5) * 4 + (lane8 & 3);     // 0..31
    const int d0 = dg * 2;
    const int e0 = eg * 8;
    u64 kva[2][4];
    #pragma unroll
    for (int dj = 0; dj < 2; dj++)
        #pragma unroll
        for (int p = 0; p < 4; p++) kva[dj][p] = 0ull;

    __syncthreads();

    const int tok_per_blk = NN / SPLITS;            // 256
    #pragma unroll 1
    for (int c = 0; c < tok_per_blk / CT; c++) {    // 2 chunks
        const int tbase = s * tok_per_blk + c * CT;
        const float* xg = x + ((size_t)b * NN + tbase) * 64;

        __syncthreads();    // previous chunk's vs readers done
        #pragma unroll
        for (int r = 0; r < 32; r++) {
            int idx = tid + r * 256;
            xs[(idx >> 6) * XSS + (idx & 63)] = xg[idx];
        }
        __syncthreads();

        // ---- projection: 8 tokens (t = tg+16j) x 8 outputs, i-pair loads ----
        u64 acc[8][4];
        #pragma unroll
        for (int j = 0; j < 8; j++)
            #pragma unroll
            for (int p = 0; p < 4; p++) acc[j][p] = 0ull;

        #pragma unroll 2
        for (int i2 = 0; i2 < 32; i2++) {
            const int i = 2 * i2;
            ulonglong2 wa0 = *(const ulonglong2*)&W[i * 64 + o0];
            ulonglong2 wa1 = *(const ulonglong2*)&W[i * 64 + o0 + 4];
            ulonglong2 wb0 = *(const ulonglong2*)&W[(i + 1) * 64 + o0];
            ulonglong2 wb1 = *(const ulonglong2*)&W[(i + 1) * 64 + o0 + 4];
            u64 w0[4] = { wa0.x, wa0.y, wa1.x, wa1.y };
            u64 w1[4] = { wb0.x, wb0.y, wb1.x, wb1.y };
            #pragma unroll
            for (int j = 0; j < 8; j++) {
                u64 xp = *(const u64*)&xs[(tg + 16 * j) * XSS + i];
                float2 xf = up2(xp);
                u64 xl = pk2(xf.x, xf.x);
                u64 xh = pk2(xf.y, xf.y);
                #pragma unroll
                for (int p = 0; p < 4; p++) {
                    fma2(acc[j][p], xl, w0[p]);
                    fma2(acc[j][p], xh, w1[p]);
                }
            }
        }
        __syncthreads();    // xs reads done (v-warps will overwrite it)

        // ---- LN in registers (8-lane groups via xor 4/8/16) + RoPE for k ----
        #pragma unroll
        for (int j = 0; j < 8; j++) {
            const int t = tg + 16 * j;
            u64 t01 = add2(acc[j][0], acc[j][1]);
            u64 t23 = add2(acc[j][2], acc[j][3]);
            float2 sf = up2(add2(t01, t23));
            float s1 = sf.x + sf.y;
            u64 q01 = add2(mul2(acc[j][0], acc[j][0]), mul2(acc[j][1], acc[j][1]));
            u64 q23 = add2(mul2(acc[j][2], acc[j][2]), mul2(acc[j][3], acc[j][3]));
            float2 qf = up2(add2(q01, q23));
            float s2 = qf.x + qf.y;
            #pragma unroll
            for (int m = 4; m <= 16; m <<= 1) {
                s1 += __shfl_xor_sync(0xffffffffu, s1, m);
                s2 += __shfl_xor_sync(0xffffffffu, s2, m);
            }
            float mean = s1 * (1.f / 64.f);
            float var  = fmaxf(s2 * (1.f / 64.f) - mean * mean, 0.f);
            float rs   = rsqrtf(var + 1e-5f);
            float mr   = -mean * rs;
            u64 rs2 = pk2(rs, rs), mr2 = pk2(mr, mr);
            u64 kn[4];
            #pragma unroll
            for (int p = 0; p < 4; p++) { kn[p] = mr2; fma2(kn[p], acc[j][p], rs2); }

            if (kwarp) {   // RoPE (warp-uniform branch); partner = og^4 -> lane^16
                u64 pn[4];
                #pragma unroll
                for (int p = 0; p < 4; p++)
                    pn[p] = __shfl_xor_sync(0xffffffffu, kn[p], 16);
                const float* tc = &g_tabc[((size_t)(b * NN + tbase + t)) * 32 + fbase];
                const float* ts = &g_tabs[((size_t)(b * NN + tbase + t)) * 32 + fbase];
                float4 c0 = *(const float4*)tc;
                float4 c1 = *(const float4*)(tc + 4);
                float4 s0 = *(const float4*)ts;
                float4 s1v = *(const float4*)(ts + 4);
                u64 cc[4] = { pk2(c0.x, c0.y), pk2(c0.z, c0.w),
                              pk2(c1.x, c1.y), pk2(c1.z, c1.w) };
                u64 ss[4] = { pk2(s0.x, s0.y), pk2(s0.z, s0.w),
                              pk2(s1v.x, s1v.y), pk2(s1v.z, s1v.w) };
                #pragma unroll
                for (int p = 0; p < 4; p++) {
                    u64 r = mul2(kn[p], cc[p]);
                    fma2(r, pn[p], mul2(ss[p], sgn2));
                    kn[p] = r;
                }
            }
            #pragma unroll
            for (int sr = 0; sr < 4; sr++) {       // rotated store order
                int p = (sr + og) & 3;
                *(u64*)&dstbuf[t * XSS + o0 + 2 * p] = kn[p];
            }
        }
        __syncthreads();

        // ---- kv[d][e] += sum_t k[t][d]*v[t][e] ----
        #pragma unroll 8
        for (int t = 0; t < CT; t++) {
            u64 kp = *(const u64*)&ks[t * XSS + d0];
            float2 kf = up2(kp);
            u64 kk0 = pk2(kf.x, kf.x), kk1 = pk2(kf.y, kf.y);
            ulonglong2 v0 = *(const ulonglong2*)&xs[t * XSS + e0];
            ulonglong2 v1 = *(const ulonglong2*)&xs[t * XSS + e0 + 4];
            u64 vp[4] = { v0.x, v0.y, v1.x, v1.y };
            #pragma unroll
            for (int p = 0; p < 4; p++) {
                fma2(kva[0][p], kk0, vp[p]);
                fma2(kva[1][p], kk1, vp[p]);
            }
        }
    }

    float* dst = g_kv_part + ((size_t)((b * HH + h) * SPLITS + s)) * 4096;
    #pragma unroll
    for (int dj = 0; dj < 2; dj++)
        #pragma unroll
        for (int p = 0; p < 4; p++)
            *(u64*)&dst[(d0 + dj) * 64 + e0 + 2 * p] = kva[dj][p];
}

// =====================================================================
// Kernel B: reduce splits, M_h = (kv_h @ Wo_h) / N
// =====================================================================
__global__ __launch_bounds__(256, 1)
void m_kernel(const float* __restrict__ Wo)
{
    __shared__ float kvs[64 * 66];
    __shared__ float wo[64 * 64];
    const int tid = threadIdx.x;
    const int h = blockIdx.x, b = blockIdx.y;
    const float* src = g_kv_part + (size_t)(b * HH + h) * SPLITS * 4096;

    #pragma unroll
    for (int r = 0; r < 16; r++) {
        int idx = tid + r * 256;
        float acc = 0.f;
        #pragma unroll 4
        for (int s = 0; s < SPLITS; s++) acc += src[s * 4096 + idx];
        int i = idx >> 6, j = idx & 63;
        kvs[i * 66 + j] = acc;
        wo[idx] = Wo[(h * 64 + i) * 64 + j];
    }
    __syncthreads();

    const int i0 = (tid >> 3) * 2;
    const int d0 = (tid & 7) * 8;
    u64 a[2][4];
    #pragma unroll
    for (int ij = 0; ij < 2; ij++)
        #pragma unroll
        for (int p = 0; p < 4; p++) a[ij][p] = 0ull;

    #pragma unroll 8
    for (int j = 0; j < 64; j++) {
        float k0 = kvs[i0 * 66 + j], k1 = kvs[(i0 + 1) * 66 + j];
        u64 p0 = pk2(k0, k0), p1 = pk2(k1, k1);
        ulonglong2 w0 = *(const ulonglong2*)&wo[j * 64 + d0];
        ulonglong2 w1 = *(const ulonglong2*)&wo[j * 64 + d0 + 4];
        u64 wp[4] = { w0.x, w0.y, w1.x, w1.y };
        #pragma unroll
        for (int p = 0; p < 4; p++) {
            fma2(a[0][p], p0, wp[p]);
            fma2(a[1][p], p1, wp[p]);
        }
    }
    const float sc = 1.f / (float)NN;
    const u64 sc2 = pk2(sc, sc);
    float* dst = g_M + ((size_t)(b * 512 + h * 64)) * 64;
    #pragma unroll
    for (int ij = 0; ij < 2; ij++)
        #pragma unroll
        for (int p = 0; p < 4; p++)
            *(u64*)&dst[(i0 + ij) * 64 + d0 + 2 * p] = mul2(a[ij][p], sc2);
}

// =====================================================================
// Kernel C: out = sum_h RoPE(x @ Wq_h) @ M_h
// smem: xs[128][68] + qs[128][68] + wq[64][64] + mm[64][64] = 100 KB
// =====================================================================
__global__ __launch_bounds__(256, 2)
void out_kernel(const float* __restrict__ x,
                const float* __restrict__ Wq, float* __restrict__ out)
{
    extern __shared__ float sm[];
    float* xs = sm;
    float* qs = sm + CT * XSS;
    float* wq = sm + 2 * CT * XSS;
    float* mm = wq + 4096;

    const int tid = threadIdx.x;
    const int b = blockIdx.y;
    const int tbase = blockIdx.x * CT;
    const float* xg = x + ((size_t)b * NN + tbase) * 64;

    #pragma unroll
    for (int r = 0; r < 32; r++) {
        int idx = tid + r * 256;
        xs[(idx >> 6) * XSS + (idx & 63)] = xg[idx];
    }

    const int lane = tid & 31;
    const int w8   = tid >> 5;          // 0..7
    const int og   = lane >> 2;         // 0..7 (high lane bits)
    const int tl   = lane & 3;
    const int tg   = w8 * 4 + tl;       // 0..31 token group
    const int o0   = og * 8;
    const float sgn = (og < 4) ? -1.f : 1.f;
    const u64 sgn2 = pk2(sgn, sgn);
    const int fbase = o0 & 31;

    u64 oa[4][4];
    #pragma unroll
    for (int j = 0; j < 4; j++)
        #pragma unroll
        for (int p = 0; p < 4; p++) oa[j][p] = 0ull;

    __syncthreads();

    #pragma unroll 1
    for (int h = 0; h < HH; h++) {
        #pragma unroll
        for (int r = 0; r < 16; r++) {
            int idx = tid + r * 256;
            int i = idx >> 6, o = idx & 63;
            wq[idx] = Wq[i * 512 + h * 64 + o];
            mm[idx] = g_M[(size_t)(b * 512 + h * 64 + i) * 64 + o];
        }
        __syncthreads();

        // q = x @ Wq_h : 4 tokens (t = tg+32j) x 8 outputs, i-pair loads
        u64 aq[4][4];
        #pragma unroll
        for (int j = 0; j < 4; j++)
            #pragma unroll
            for (int p = 0; p < 4; p++) aq[j][p] = 0ull;

        #pragma unroll 2
        for (int i2 = 0; i2 < 32; i2++) {
            const int i = 2 * i2;
            ulonglong2 wa0 = *(const ulonglong2*)&wq[i * 64 + o0];
            ulonglong2 wa1 = *(const ulonglong2*)&wq[i * 64 + o0 + 4];
            ulonglong2 wb0 = *(const ulonglong2*)&wq[(i + 1) * 64 + o0];
            ulonglong2 wb1 = *(const ulonglong2*)&wq[(i + 1) * 64 + o0 + 4];
            u64 w0[4] = { wa0.x, wa0.y, wa1.x, wa1.y };
            u64 w1[4] = { wb0.x, wb0.y, wb1.x, wb1.y };
            #pragma unroll
            for (int j = 0; j < 4; j++) {
                u64 xp = *(const u64*)&xs[(tg + 32 * j) * XSS + i];
                float2 xf = up2(xp);
                u64 xl = pk2(xf.x, xf.x);
                u64 xh = pk2(xf.y, xf.y);
                #pragma unroll
                for (int p = 0; p < 4; p++) {
                    fma2(aq[j][p], xl, w0[p]);
                    fma2(aq[j][p], xh, w1[p]);
                }
            }
        }

        // RoPE(q) in registers, single store to qs
        #pragma unroll
        for (int j = 0; j < 4; j++) {
            const int t = tg + 32 * j;
            u64 pn[4];
            #pragma unroll
            for (int p = 0; p < 4; p++)
                pn[p] = __shfl_xor_sync(0xffffffffu, aq[j][p], 16);
            const float* tc = &g_tabc[((size_t)(b * NN + tbase + t)) * 32 + fbase];
            const float* ts = &g_tabs[((size_t)(b * NN + tbase + t)) * 32 + fbase];
            float4 c0 = *(const float4*)tc;
            float4 c1 = *(const float4*)(tc + 4);
            float4 s0 = *(const float4*)ts;
            float4 s1v = *(const float4*)(ts + 4);
            u64 cc[4] = { pk2(c0.x, c0.y), pk2(c0.z, c0.w),
                          pk2(c1.x, c1.y), pk2(c1.z, c1.w) };
            u64 ss[4] = { pk2(s0.x, s0.y), pk2(s0.z, s0.w),
                          pk2(s1v.x, s1v.y), pk2(s1v.z, s1v.w) };
            #pragma unroll
            for (int sr = 0; sr < 4; sr++) {
                int p = (sr + og) & 3;
                u64 r = mul2(aq[j][p], cc[p]);
                fma2(r, pn[p], mul2(ss[p], sgn2));
                *(u64*)&qs[t * XSS + o0 + 2 * p] = r;
            }
        }
        __syncthreads();

        // out += q_rope @ M_h  (i-pair loads from qs)
        #pragma unroll 2
        for (int i2 = 0; i2 < 32; i2++) {
            const int i = 2 * i2;
            ulonglong2 ma0 = *(const ulonglong2*)&mm[i * 64 + o0];
            ulonglong2 ma1 = *(const ulonglong2*)&mm[i * 64 + o0 + 4];
            ulonglong2 mb0 = *(const ulonglong2*)&mm[(i + 1) * 64 + o0];
            ulonglong2 mb1 = *(const ulonglong2*)&mm[(i + 1) * 64 + o0 + 4];
            u64 m0[4] = { ma0.x, ma0.y, ma1.x, ma1.y };
            u64 m1[4] = { mb0.x, mb0.y, mb1.x, mb1.y };
            #pragma unroll
            for (int j = 0; j < 4; j++) {
                u64 qp = *(const u64*)&qs[(tg + 32 * j) * XSS + i];
                float2 qf = up2(qp);
                u64 ql = pk2(qf.x, qf.x);
                u64 qh = pk2(qf.y, qf.y);
                #pragma unroll
                for (int p = 0; p < 4; p++) {
                    fma2(oa[j][p], ql, m0[p]);
                    fma2(oa[j][p], qh, m1[p]);
                }
            }
        }
        __syncthreads();
    }

    float* outg = out + ((size_t)b * NN + tbase) * 64;
    #pragma unroll
    for (int j = 0; j < 4; j++)
        #pragma unroll
        for (int p = 0; p < 4; p++)
            *(u64*)&outg[(tg + 32 * j) * 64 + o0 + 2 * p] = oa[j][p];
}

// =====================================================================
extern "C" void kernel_launch(void* const* d_in, const int* in_sizes, int n_in,
                              void* d_out, int out_size)
{
    const float* x   = (const float*)d_in[0];
    const float* pos = (const float*)d_in[1];
    const float* Wq  = (const float*)d_in[2];
    const float* Wk  = (const float*)d_in[3];
    const float* Wv  = (const float*)d_in[4];
    const float* Wo  = (const float*)d_in[5];
    float* out = (float*)d_out;

    const int SMEM_KV  = (2 * CT * XSS + 2 * 4096) * 4;   // 102400 B
    const int SMEM_OUT = (2 * CT * XSS + 2 * 4096) * 4;   // 102400 B
    cudaFuncSetAttribute(kv_kernel,  cudaFuncAttributeMaxDynamicSharedMemorySize, SMEM_KV);
    cudaFuncSetAttribute(out_kernel, cudaFuncAttributeMaxDynamicSharedMemorySize, SMEM_OUT);

    tab_kernel<<<BB * NN * 32 / 256, 256>>>(pos);
    kv_kernel<<<dim3(SPLITS, HH, BB), 256, SMEM_KV>>>(x, Wk, Wv);
    m_kernel<<<dim3(HH, BB), 256>>>(Wo);
    out_kernel<<<dim3(NN / CT, BB), 256, SMEM_OUT>>>(x, Wq, out);
}